// round 1
// baseline (speedup 1.0000x reference)
#include <cuda_runtime.h>
#include <math.h>

// Problem constants
#define B_  512
#define F_  1280
#define H_  2560
#define K_  8
#define E_  9

// GEMM1 tiling
#define BM 128
#define BN 128
#define BK 16
#define TM 8
#define TN 8
// 256 threads = 16x16 thread grid

// Scratch for h = relu(x@W1 + b1): [E, B, H] fp32 = 47.2 MB (static device global; no runtime alloc)
__device__ float g_h[(size_t)E_ * B_ * H_];

__global__ __launch_bounds__(256, 2)
void gemm1_relu_kernel(const float* __restrict__ x,
                       const float* __restrict__ W1,
                       const float* __restrict__ b1)
{
    __shared__ float As[BK][BM];       // [k][m]
    __shared__ float Bs[BK][BN];       // [k][n]

    const int e  = blockIdx.z;
    const int m0 = blockIdx.y * BM;    // batch rows
    const int n0 = blockIdx.x * BN;    // H cols

    const float* __restrict__ A  = x;                              // [B_, F_]
    const float* __restrict__ Bm = W1 + (size_t)e * F_ * H_;       // [F_, H_]

    const int tid = threadIdx.x;       // 0..255
    const int tx  = tid & 15;          // 0..15 -> N
    const int ty  = tid >> 4;          // 0..15 -> M

    float acc[TM][TN];
#pragma unroll
    for (int i = 0; i < TM; i++)
#pragma unroll
        for (int j = 0; j < TN; j++) acc[i][j] = 0.0f;

    for (int k0 = 0; k0 < F_; k0 += BK) {
        // Load A tile: 128 rows x 16 k = 512 float4, 2 per thread
#pragma unroll
        for (int s = 0; s < 2; s++) {
            int i  = tid + s * 256;
            int r  = i >> 2;            // 0..127
            int kq = (i & 3) * 4;       // 0,4,8,12
            float4 v = *(const float4*)&A[(size_t)(m0 + r) * F_ + k0 + kq];
            As[kq + 0][r] = v.x;
            As[kq + 1][r] = v.y;
            As[kq + 2][r] = v.z;
            As[kq + 3][r] = v.w;
        }
        // Load B tile: 16 rows x 128 n = 512 float4, 2 per thread
#pragma unroll
        for (int s = 0; s < 2; s++) {
            int i = tid + s * 256;
            int r = i >> 5;             // 0..15
            int c = (i & 31) * 4;       // 0..124
            *(float4*)&Bs[r][c] = *(const float4*)&Bm[(size_t)(k0 + r) * H_ + n0 + c];
        }
        __syncthreads();

#pragma unroll
        for (int kk = 0; kk < BK; kk++) {
            float a[TM], b[TN];
#pragma unroll
            for (int i = 0; i < TM; i += 4) {
                float4 v = *(const float4*)&As[kk][ty * TM + i];
                a[i + 0] = v.x; a[i + 1] = v.y; a[i + 2] = v.z; a[i + 3] = v.w;
            }
#pragma unroll
            for (int j = 0; j < TN; j += 4) {
                float4 v = *(const float4*)&Bs[kk][tx * TN + j];
                b[j + 0] = v.x; b[j + 1] = v.y; b[j + 2] = v.z; b[j + 3] = v.w;
            }
#pragma unroll
            for (int i = 0; i < TM; i++)
#pragma unroll
                for (int j = 0; j < TN; j++)
                    acc[i][j] = fmaf(a[i], b[j], acc[i][j]);
        }
        __syncthreads();
    }

    // Epilogue: + b1, ReLU, store to g_h[e, b, h]
    const float* __restrict__ bias = b1 + (size_t)e * H_ + n0 + tx * TN;
    float bl[TN];
#pragma unroll
    for (int j = 0; j < TN; j += 4) {
        float4 v = *(const float4*)&bias[j];
        bl[j + 0] = v.x; bl[j + 1] = v.y; bl[j + 2] = v.z; bl[j + 3] = v.w;
    }
    float* __restrict__ hout = g_h + (size_t)e * B_ * H_;
#pragma unroll
    for (int i = 0; i < TM; i++) {
        int brow = m0 + ty * TM + i;
        float* dst = hout + (size_t)brow * H_ + n0 + tx * TN;
#pragma unroll
        for (int j = 0; j < TN; j += 4) {
            float4 v;
            v.x = fmaxf(acc[i][j + 0] + bl[j + 0], 0.0f);
            v.y = fmaxf(acc[i][j + 1] + bl[j + 1], 0.0f);
            v.z = fmaxf(acc[i][j + 2] + bl[j + 2], 0.0f);
            v.w = fmaxf(acc[i][j + 3] + bl[j + 3], 0.0f);
            *(float4*)&dst[j] = v;
        }
    }
}

// One block per batch row b. Computes logits[e,b,:] for all 9 experts,
// softmax per expert, then leaf path products. Writes both outputs.
// Output layout: [0 .. B*73)           leaf_probs [B,73] row-major
//                [B*73 .. B*73+E*B*K)  logits     [E,B,K] row-major
__global__ __launch_bounds__(256)
void tail_kernel(const float* __restrict__ W2,
                 const float* __restrict__ b2,
                 float* __restrict__ out)
{
    const int b   = blockIdx.x;
    const int tid = threadIdx.x;
    const int warp = tid >> 5;
    const int lane = tid & 31;

    __shared__ float hs[H_];
    __shared__ float logits_s[E_][K_];
    __shared__ float probs_s[E_][K_];

    for (int e = 0; e < E_; e++) {
        // load h[e, b, :] (2560 floats = 640 float4) cooperatively
        const float* hrow = g_h + ((size_t)e * B_ + b) * H_;
        for (int i = tid; i < H_ / 4; i += 256) {
            *(float4*)&hs[i * 4] = *(const float4*)&hrow[i * 4];
        }
        __syncthreads();

        if (warp < K_) {
            const int k = warp;
            const float* __restrict__ w2 = W2 + (size_t)e * H_ * K_;
            float sum = 0.0f;
#pragma unroll 4
            for (int i = lane; i < H_; i += 32)
                sum = fmaf(hs[i], w2[(size_t)i * K_ + k], sum);
#pragma unroll
            for (int o = 16; o > 0; o >>= 1)
                sum += __shfl_xor_sync(0xFFFFFFFFu, sum, o);
            if (lane == 0) {
                float lv = sum + b2[e * K_ + k];
                logits_s[e][k] = lv;
                out[(size_t)B_ * 73 + ((size_t)e * B_ + b) * K_ + k] = lv;
            }
        }
        __syncthreads();
    }

    // softmax per expert (9 threads, each over 8 values)
    if (tid < E_) {
        float m = -INFINITY;
#pragma unroll
        for (int k = 0; k < K_; k++) m = fmaxf(m, logits_s[tid][k]);
        float ex[K_];
        float s = 0.0f;
#pragma unroll
        for (int k = 0; k < K_; k++) { ex[k] = expf(logits_s[tid][k] - m); s += ex[k]; }
        float inv = 1.0f / s;
#pragma unroll
        for (int k = 0; k < K_; k++) probs_s[tid][k] = ex[k] * inv;
    }
    __syncthreads();

    // leaf path products: 73 values per batch row
    if (tid < 73) {
        float v;
        if (tid == 0) {
            v = 1.0f;
        } else if (tid < 9) {
            v = probs_s[0][tid - 1];
        } else {
            int t  = tid - 9;
            int c1 = t >> 3;
            int c2 = t & 7;
            v = probs_s[0][c1] * probs_s[1 + c1][c2];
        }
        out[(size_t)b * 73 + tid] = v;
    }
}

extern "C" void kernel_launch(void* const* d_in, const int* in_sizes, int n_in,
                              void* d_out, int out_size)
{
    const float* x  = (const float*)d_in[0];   // [512,1280]
    const float* W1 = (const float*)d_in[1];   // [9,1280,2560]
    const float* b1 = (const float*)d_in[2];   // [9,2560]
    const float* W2 = (const float*)d_in[3];   // [9,2560,8]
    const float* b2 = (const float*)d_in[4];   // [9,8]
    float* out = (float*)d_out;                // 512*73 + 9*512*8 = 74240 floats

    dim3 grid1(H_ / BN, B_ / BM, E_);          // (20, 4, 9)
    gemm1_relu_kernel<<<grid1, 256>>>(x, W1, b1);

    tail_kernel<<<B_, 256>>>(W2, b2, out);
}